// round 16
// baseline (speedup 1.0000x reference)
#include <cuda_runtime.h>
#include <cuda_fp16.h>
#include <math.h>
#include <stdint.h>

#define BB 8
#define CC 512
#define TT 1024
#define HEADS 8
#define CH 64
#define GROUPS 32
#define CPG 16
#define GN_EPS 1e-5f

// ---------------- scratch (fp16) ---------------------------------------------
// GEMM operands: [k-iter][row][32 halves], SW64 swizzle: kbyte ^ ((row&6)<<3)
__device__ __align__(1024) __half g_xnT[BB * TT * CC];
__device__ __align__(1024) __half g_qkvw[3 * CC * CC];
__device__ __align__(1024) __half g_projw[CC * CC];
__device__ __align__(1024) __half g_aT[BB * TT * CC];
// Flash tiles: contiguous per tile, 128B rows, SW128 swizzle: byte ^ ((row&7)<<4)
__device__ __align__(1024) __half g_qblk[BB * HEADS * 8 * 128 * 64];
__device__ __align__(1024) __half g_kblk[BB * HEADS * 16 * 64 * 64];
__device__ __align__(1024) __half g_vblk[BB * HEADS * 16 * 64 * 64];

// ---------------- helpers ----------------------------------------------------
__device__ __forceinline__ uint32_t smem_u32(const void* p) {
    uint32_t a;
    asm("{ .reg .u64 t; cvta.to.shared.u64 t, %1; cvt.u32.u64 %0, t; }"
        : "=r"(a) : "l"(p));
    return a;
}
__device__ __forceinline__ float warp_sum(float v) {
    #pragma unroll
    for (int o = 16; o > 0; o >>= 1) v += __shfl_down_sync(0xffffffffu, v, o);
    return v;
}
__device__ __forceinline__ uint32_t h2exp(float a, float b) {
    const float C = 0.1803368802f;    // 0.125 * log2(e)
    const float D = -5.7707801636f;   // -4 * log2(e)
    __half2 h = __floats2half2_rn(fmaf(a, C, D), fmaf(b, C, D));
    uint32_t r = *(uint32_t*)&h;
    uint32_t o;
    asm("ex2.approx.f16x2 %0, %1;" : "=r"(o) : "r"(r));
    return o;
}

#define LDM4(r0, r1, r2, r3, addr) \
    asm volatile("ldmatrix.sync.aligned.m8n8.x4.shared.b16 {%0,%1,%2,%3}, [%4];" \
                 : "=r"(r0), "=r"(r1), "=r"(r2), "=r"(r3) : "r"(addr))

#define MMA16816(d, a, b0v, b1v) \
    asm volatile("mma.sync.aligned.m16n8k16.row.col.f32.f16.f16.f32 " \
                 "{%0,%1,%2,%3}, {%4,%5,%6,%7}, {%8,%9}, {%0,%1,%2,%3};" \
                 : "+f"((d)[0]), "+f"((d)[1]), "+f"((d)[2]), "+f"((d)[3]) \
                 : "r"((a)[0]), "r"((a)[1]), "r"((a)[2]), "r"((a)[3]), \
                   "r"(b0v), "r"(b1v))

// ---------------- mbarrier + bulk copy helpers -------------------------------
__device__ __forceinline__ void mbar_init(uint32_t a, uint32_t cnt) {
    asm volatile("mbarrier.init.shared.b64 [%0], %1;" :: "r"(a), "r"(cnt) : "memory");
}
__device__ __forceinline__ void mbar_expect_tx(uint32_t a, uint32_t bytes) {
    asm volatile("mbarrier.arrive.expect_tx.shared.b64 _, [%0], %1;"
                 :: "r"(a), "r"(bytes) : "memory");
}
__device__ __forceinline__ void mbar_arrive(uint32_t a) {
    asm volatile("mbarrier.arrive.shared.b64 _, [%0];" :: "r"(a) : "memory");
}
__device__ __forceinline__ void mbar_wait(uint32_t a, uint32_t phase) {
    asm volatile(
        "{\n\t.reg .pred P;\n\t"
        "WL%=:\n\t"
        "mbarrier.try_wait.parity.acquire.cta.shared::cta.b64 P, [%0], %1, 0x989680;\n\t"
        "@P bra.uni WD%=;\n\t"
        "bra.uni WL%=;\n\t"
        "WD%=:\n\t}"
        :: "r"(a), "r"(phase) : "memory");
}
__device__ __forceinline__ void bulk_g2s(uint32_t dst, const void* src,
                                         uint32_t bytes, uint32_t mbar) {
    asm volatile(
        "cp.async.bulk.shared::cluster.global.mbarrier::complete_tx::bytes "
        "[%0], [%1], %2, [%3];"
        :: "r"(dst), "l"(src), "r"(bytes), "r"(mbar) : "memory");
}

// ---------------- fused GroupNorm (+ weight cvt tail, blocked outputs) -------
#define GN_PAD 1033
__global__ __launch_bounds__(512) void gn_fused_kernel(
    const float* __restrict__ x, const float* __restrict__ w,
    const float* __restrict__ bias,
    const float* __restrict__ qkvw, const float* __restrict__ projw) {
    extern __shared__ float sbuf[];
    const int bg = blockIdx.x;
    const int tid = threadIdx.x;
    const float* p = x + (long)bg * CPG * TT;

    float s = 0.f, ss = 0.f;
    #pragma unroll
    for (int i = tid; i < CPG * TT; i += 512) {
        float v = p[i];
        sbuf[(i >> 10) * GN_PAD + (i & 1023)] = v;
        s += v; ss += v * v;
    }
    __shared__ float shs[16], shss[16], bc[2];
    int lane = tid & 31, wid = tid >> 5;
    s = warp_sum(s); ss = warp_sum(ss);
    if (lane == 0) { shs[wid] = s; shss[wid] = ss; }
    __syncthreads();
    if (tid < 32) {
        s  = (lane < 16) ? shs[lane]  : 0.f;
        ss = (lane < 16) ? shss[lane] : 0.f;
        s = warp_sum(s); ss = warp_sum(ss);
        if (lane == 0) {
            const float inv_n = 1.f / (float)(CPG * TT);
            float mu = s * inv_n;
            float var = ss * inv_n - mu * mu;
            bc[0] = mu;
            bc[1] = rsqrtf(var + GN_EPS);
        }
    }
    __syncthreads();
    const float mu = bc[0], rs = bc[1];
    const int b = bg >> 5, g = bg & 31;
    const int cl = tid & 15;
    const int c = g * CPG + cl;
    const float wc = w[c] * rs;
    const float bb = bias[c] - mu * wc;
    char* xbase = (char*)g_xnT + ((long)b * 16 + (c >> 5)) * 65536;
    const int k2 = (c & 31) * 2;
    #pragma unroll
    for (int j = tid; j < CPG * TT; j += 512) {
        int t = j >> 4;
        float v = sbuf[cl * GN_PAD + t];
        long off = (long)t * 64 + (k2 ^ ((t & 6) << 3));
        *(__half*)(xbase + off) = __float2half(fmaf(v, wc, bb));
    }
    for (int i = bg * 512 + tid; i < 4 * CC * CC; i += 256 * 512) {
        if (i < 3 * CC * CC) {
            int m = i >> 9, cc2 = i & 511;
            long off = (long)(cc2 >> 5) * 98304 + (long)m * 64 +
                       (((cc2 & 31) * 2) ^ ((m & 6) << 3));
            *(__half*)((char*)g_qkvw + off) = __float2half(qkvw[i]);
        } else {
            int j = i - 3 * CC * CC;
            int m = j >> 9, cc2 = j & 511;
            long off = (long)(cc2 >> 5) * 32768 + (long)m * 64 +
                       (((cc2 & 31) * 2) ^ ((m & 6) << 3));
            *(__half*)((char*)g_projw + off) = __float2half(projw[j]);
        }
    }
}

#define EPI_STRIDE 136

// ---------------- QKV GEMM (512 threads, 4x4 warp grid, bulk ring) -----------
#define QKV_STAGE 16384
__global__ __launch_bounds__(512) void gemm_qkv_kernel(const float* __restrict__ bias) {
    extern __shared__ char smem[];
    constexpr int BM = 128, BN = 128, NT = 4;
    const uint32_t sb = smem_u32(smem);
    const uint32_t MB = sb + 4 * QKV_STAGE;
    const int tid = threadIdx.x;
    const int wid = tid >> 5, lane = tid & 31;
    const int wm = wid & 3, wn = wid >> 2;     // 4m x 4n of 32x32 tiles

    const int m0 = blockIdx.y * BM;
    const int n0 = blockIdx.x * BN;
    const int z = blockIdx.z;

    const char* Asrc = (const char*)g_qkvw + (long)m0 * 64;
    const char* Bsrc = (const char*)g_xnT + (long)z * 16 * 65536 + (long)n0 * 64;

    if (tid == 0) {
        #pragma unroll
        for (int s = 0; s < 4; ++s) { mbar_init(MB + s * 8, 1); mbar_init(MB + 32 + s * 8, 512); }
    }
    __syncthreads();
    if (tid == 0) {
        #pragma unroll
        for (int s = 0; s < 3; ++s) {
            mbar_expect_tx(MB + s * 8, QKV_STAGE);
            bulk_g2s(sb + s * QKV_STAGE, Asrc + (long)s * 98304, BM * 64, MB + s * 8);
            bulk_g2s(sb + s * QKV_STAGE + BM * 64, Bsrc + (long)s * 65536, BN * 64, MB + s * 8);
        }
    }

    float acc[2][NT][4] = {};
    const uint32_t a_row = (uint32_t)(wm * 32 + (lane & 15)) * 64;
    const uint32_t a_ch  = (uint32_t)((lane >> 4) << 4);
    const uint32_t b_row = (uint32_t)(wn * 32 + ((lane >> 4) << 3) + (lane & 7)) * 64;
    const uint32_t b_ch  = (uint32_t)(((lane >> 3) & 1) << 4);
    const uint32_t swa = ((a_row >> 6) & 6) << 3;
    const uint32_t swb = ((b_row >> 6) & 6) << 3;

    for (int i = 0; i < 16; ++i) {
        if (tid == 0 && i + 3 < 16) {
            int bu = (i + 3) & 3;
            if (i >= 1) mbar_wait(MB + 32 + bu * 8, ((i - 1) >> 2) & 1);
            mbar_expect_tx(MB + bu * 8, QKV_STAGE);
            bulk_g2s(sb + bu * QKV_STAGE, Asrc + (long)(i + 3) * 98304, BM * 64, MB + bu * 8);
            bulk_g2s(sb + bu * QKV_STAGE + BM * 64, Bsrc + (long)(i + 3) * 65536, BN * 64, MB + bu * 8);
        }
        mbar_wait(MB + (i & 3) * 8, (i >> 2) & 1);
        const uint32_t sA = sb + (i & 3) * QKV_STAGE;
        const uint32_t sB = sA + BM * 64;
        #pragma unroll
        for (int half = 0; half < 2; ++half) {
            uint32_t af[2][4];
            #pragma unroll
            for (int mi = 0; mi < 2; ++mi) {
                uint32_t ad = sA + a_row + mi * 1024 + (((uint32_t)(half * 32) + a_ch) ^ swa);
                LDM4(af[mi][0], af[mi][1], af[mi][2], af[mi][3], ad);
            }
            uint32_t bf[NT][2];
            #pragma unroll
            for (int g = 0; g < 2; ++g) {
                uint32_t bd = sB + b_row + g * 1024 + (((uint32_t)(half * 32) + b_ch) ^ swb);
                LDM4(bf[2 * g][0], bf[2 * g][1], bf[2 * g + 1][0], bf[2 * g + 1][1], bd);
            }
            #pragma unroll
            for (int mi = 0; mi < 2; ++mi)
                #pragma unroll
                for (int ni = 0; ni < NT; ++ni)
                    MMA16816(acc[mi][ni], af[mi], bf[ni][0], bf[ni][1]);
        }
        mbar_arrive(MB + 32 + (i & 3) * 8);
    }
    __syncthreads();

    const int lr = lane >> 2;
    const int lc = (lane & 3) * 2;
    __half* stg = (__half*)smem;
    #pragma unroll
    for (int mi = 0; mi < 2; ++mi) {
        #pragma unroll
        for (int rs = 0; rs < 2; ++rs) {
            const int rl = wm * 32 + mi * 16 + rs * 8 + lr;
            const int r = m0 + rl;
            float bv = bias[r];
            int rm = r % 192;
            int h = r / 192;
            bool isv = (rm >= 128);
            #pragma unroll
            for (int ni = 0; ni < NT; ++ni) {
                int cl = wn * 32 + ni * 8 + lc;
                __half h0 = __float2half(acc[mi][ni][rs * 2 + 0] + bv);
                __half h1 = __float2half(acc[mi][ni][rs * 2 + 1] + bv);
                stg[cl * EPI_STRIDE + rl] = h0;
                stg[(cl + 1) * EPI_STRIDE + rl] = h1;
                if (isv) {
                    int c = n0 + cl;
                    int ch = rm - 128;
                    long vb = (((long)(z * 8 + h) * 16) + (c >> 6)) * 8192;
                    long off = vb + (long)ch * 128 + (((c & 63) * 2) ^ ((ch & 7) << 4));
                    *(__half2*)((char*)g_vblk + off) = __halves2half2(h0, h1);
                }
            }
        }
    }
    __syncthreads();
    #pragma unroll
    for (int task = tid; task < BN * 16; task += 512) {
        int cl = task >> 4, seg = task & 15;
        int m = m0 + seg * 8;
        int rm = m % 192;
        if (rm < 128) {
            int h = m / 192;
            int tg = n0 + cl;
            uint4 v = *(uint4*)&stg[cl * EPI_STRIDE + seg * 8];
            if (rm < 64) {
                long qb = (((long)(z * 8 + h) * 8) + (tg >> 7)) * 16384;
                int r = tg & 127;
                long off = qb + (long)r * 128 + ((rm * 2) ^ ((r & 7) << 4));
                *(uint4*)((char*)g_qblk + off) = v;
            } else {
                long kb = (((long)(z * 8 + h) * 16) + (tg >> 6)) * 8192;
                int tok = tg & 63;
                long off = kb + (long)tok * 128 + (((rm - 64) * 2) ^ ((tok & 7) << 4));
                *(uint4*)((char*)g_kblk + off) = v;
            }
        }
    }
}

// ---------------- PROJ GEMM (512 threads, 4x4 warp grid, bulk ring) ----------
#define PROJ_STAGE 24576
__global__ __launch_bounds__(512) void gemm_proj_kernel(
    const float* __restrict__ bias, const float* __restrict__ xres,
    float* __restrict__ out) {
    extern __shared__ char smem[];
    constexpr int BM = 128, BN = 256, NT = 8;
    const uint32_t sb = smem_u32(smem);
    const uint32_t MB = sb + 4 * PROJ_STAGE;
    const int tid = threadIdx.x;
    const int wid = tid >> 5, lane = tid & 31;
    const int wm = wid & 3, wn = wid >> 2;     // 4m x 4n of 32x64 tiles

    const int m0 = blockIdx.y * BM;
    const int n0 = blockIdx.x * BN;
    const int z = blockIdx.z;

    const char* Asrc = (const char*)g_projw + (long)m0 * 64;
    const char* Bsrc = (const char*)g_aT + (long)z * 16 * 65536 + (long)n0 * 64;

    if (tid == 0) {
        #pragma unroll
        for (int s = 0; s < 4; ++s) { mbar_init(MB + s * 8, 1); mbar_init(MB + 32 + s * 8, 512); }
    }
    __syncthreads();
    if (tid == 0) {
        #pragma unroll
        for (int s = 0; s < 3; ++s) {
            mbar_expect_tx(MB + s * 8, PROJ_STAGE);
            bulk_g2s(sb + s * PROJ_STAGE, Asrc + (long)s * 32768, BM * 64, MB + s * 8);
            bulk_g2s(sb + s * PROJ_STAGE + BM * 64, Bsrc + (long)s * 65536, BN * 64, MB + s * 8);
        }
    }

    float acc[2][NT][4] = {};
    const uint32_t a_row = (uint32_t)(wm * 32 + (lane & 15)) * 64;
    const uint32_t a_ch  = (uint32_t)((lane >> 4) << 4);
    const uint32_t b_row = (uint32_t)(wn * 64 + ((lane >> 4) << 3) + (lane & 7)) * 64;
    const uint32_t b_ch  = (uint32_t)(((lane >> 3) & 1) << 4);
    const uint32_t swa = ((a_row >> 6) & 6) << 3;
    const uint32_t swb = ((b_row >> 6) & 6) << 3;

    for (int i = 0; i < 16; ++i) {
        if (tid == 0 && i + 3 < 16) {
            int bu = (i + 3) & 3;
            if (i >= 1) mbar_wait(MB + 32 + bu * 8, ((i - 1) >> 2) & 1);
            mbar_expect_tx(MB + bu * 8, PROJ_STAGE);
            bulk_g2s(sb + bu * PROJ_STAGE, Asrc + (long)(i + 3) * 32768, BM * 64, MB + bu * 8);
            bulk_g2s(sb + bu * PROJ_STAGE + BM * 64, Bsrc + (long)(i + 3) * 65536, BN * 64, MB + bu * 8);
        }
        mbar_wait(MB + (i & 3) * 8, (i >> 2) & 1);
        const uint32_t sA = sb + (i & 3) * PROJ_STAGE;
        const uint32_t sB = sA + BM * 64;
        #pragma unroll
        for (int half = 0; half < 2; ++half) {
            uint32_t af[2][4];
            #pragma unroll
            for (int mi = 0; mi < 2; ++mi) {
                uint32_t ad = sA + a_row + mi * 1024 + (((uint32_t)(half * 32) + a_ch) ^ swa);
                LDM4(af[mi][0], af[mi][1], af[mi][2], af[mi][3], ad);
            }
            uint32_t bf[NT][2];
            #pragma unroll
            for (int g = 0; g < 4; ++g) {
                uint32_t bd = sB + b_row + g * 1024 + (((uint32_t)(half * 32) + b_ch) ^ swb);
                LDM4(bf[2 * g][0], bf[2 * g][1], bf[2 * g + 1][0], bf[2 * g + 1][1], bd);
            }
            #pragma unroll
            for (int mi = 0; mi < 2; ++mi)
                #pragma unroll
                for (int ni = 0; ni < NT; ++ni)
                    MMA16816(acc[mi][ni], af[mi], bf[ni][0], bf[ni][1]);
        }
        mbar_arrive(MB + 32 + (i & 3) * 8);
    }

    const int lr = lane >> 2;
    const int lc = (lane & 3) * 2;
    #pragma unroll
    for (int mi = 0; mi < 2; ++mi) {
        #pragma unroll
        for (int rs = 0; rs < 2; ++rs) {
            const int r = m0 + wm * 32 + mi * 16 + rs * 8 + lr;
            float bv = bias[r];
            long rowb = ((long)z * CC + r) * TT;
            #pragma unroll
            for (int ni = 0; ni < NT; ++ni) {
                int c = n0 + wn * 64 + ni * 8 + lc;
                float2 xv = *(const float2*)&xres[rowb + c];
                float2 o = make_float2(acc[mi][ni][rs * 2 + 0] + bv + xv.x,
                                       acc[mi][ni][rs * 2 + 1] + bv + xv.y);
                *(float2*)&out[rowb + c] = o;
            }
        }
    }
}

// ---------------- flash attention (bulk async KV ring) -----------------------
#define FQB 16384
#define FSTG2 16384
#define FSMEM (FQB + 4 * FSTG2 + 64)   // 82048

__global__ __launch_bounds__(128) void flash_kernel() {
    extern __shared__ char smem[];
    const uint32_t sb = smem_u32(smem);
    const uint32_t MB = sb + FQB + 4 * FSTG2;
    const int tid = threadIdx.x, wid = tid >> 5, lane = tid & 31;
    const int qt = blockIdx.x;
    const int z = blockIdx.y;
    const int b = z >> 3, h = z & 7;
    const uint32_t ONE2 = 0x3C003C00u;

    const char* Qsrc = (const char*)g_qblk + (((long)(b * 8 + h) * 8) + qt) * 16384;
    const char* Ksrc = (const char*)g_kblk + ((long)(b * 8 + h) * 16) * 8192;
    const char* Vsrc = (const char*)g_vblk + ((long)(b * 8 + h) * 16) * 8192;

    if (tid == 0) {
        #pragma unroll
        for (int s = 0; s < 4; ++s) { mbar_init(MB + s * 8, 1); mbar_init(MB + 32 + s * 8, 128); }
    }
    __syncthreads();
    if (tid == 0) {
        mbar_expect_tx(MB + 0, FQB + FSTG2);
        bulk_g2s(sb, Qsrc, FQB, MB + 0);
        bulk_g2s(sb + FQB, Ksrc, 8192, MB + 0);
        bulk_g2s(sb + FQB + 8192, Vsrc, 8192, MB + 0);
        #pragma unroll
        for (int s = 1; s < 3; ++s) {
            mbar_expect_tx(MB + s * 8, FSTG2);
            bulk_g2s(sb + FQB + s * FSTG2, Ksrc + (long)s * 8192, 8192, MB + s * 8);
            bulk_g2s(sb + FQB + s * FSTG2 + 8192, Vsrc + (long)s * 8192, 8192, MB + s * 8);
        }
    }

    float o_acc[2][8][4] = {};
    float l_acc[2][4] = {};
    uint32_t qf[2][4][4];
    const int a_r16 = lane & 15;
    const int a_c   = (lane >> 4) << 4;
    const int b_r   = ((lane >> 4) << 3) + (lane & 7);
    const int b_c   = ((lane >> 3) & 1) << 4;

    for (int j = 0; j < 16; ++j) {
        if (tid == 0 && j + 3 < 16) {
            int bu = (j + 3) & 3;
            if (j >= 1) mbar_wait(MB + 32 + bu * 8, ((j - 1) >> 2) & 1);
            mbar_expect_tx(MB + bu * 8, FSTG2);
            bulk_g2s(sb + FQB + bu * FSTG2, Ksrc + (long)(j + 3) * 8192, 8192, MB + bu * 8);
            bulk_g2s(sb + FQB + bu * FSTG2 + 8192, Vsrc + (long)(j + 3) * 8192, 8192, MB + bu * 8);
        }
        mbar_wait(MB + (j & 3) * 8, (j >> 2) & 1);

        if (j == 0) {
            #pragma unroll
            for (int mi = 0; mi < 2; ++mi) {
                int r = wid * 32 + mi * 16 + a_r16;
                uint32_t rowb = sb + (uint32_t)r * 128;
                uint32_t swz = (uint32_t)((r & 7) << 4);
                #pragma unroll
                for (int ks = 0; ks < 4; ++ks)
                    LDM4(qf[mi][ks][0], qf[mi][ks][1], qf[mi][ks][2], qf[mi][ks][3],
                         rowb + (((uint32_t)(a_c + ks * 32)) ^ swz));
            }
        }

        const uint32_t kd = sb + FQB + (j & 3) * FSTG2;
        float s_acc[2][8][4] = {};

        #pragma unroll
        for (int ks = 0; ks < 4; ++ks) {
            uint32_t bh[8][2];
            #pragma unroll
            for (int g = 0; g < 4; ++g) {
                int tok = g * 16 + b_r;
                uint32_t ba = kd + (uint32_t)tok * 128 +
                              (((uint32_t)(b_c + ks * 32)) ^ ((uint32_t)((tok & 7) << 4)));
                LDM4(bh[2 * g][0], bh[2 * g][1], bh[2 * g + 1][0], bh[2 * g + 1][1], ba);
            }
            #pragma unroll
            for (int mi = 0; mi < 2; ++mi)
                #pragma unroll
                for (int t = 0; t < 8; ++t)
                    MMA16816(s_acc[mi][t], qf[mi][ks], bh[t][0], bh[t][1]);
        }

        uint32_t pa[2][4][4];
        #pragma unroll
        for (int mi = 0; mi < 2; ++mi)
            #pragma unroll
            for (int ks = 0; ks < 4; ++ks) {
                pa[mi][ks][0] = h2exp(s_acc[mi][2 * ks][0], s_acc[mi][2 * ks][1]);
                pa[mi][ks][1] = h2exp(s_acc[mi][2 * ks][2], s_acc[mi][2 * ks][3]);
                pa[mi][ks][2] = h2exp(s_acc[mi][2 * ks + 1][0], s_acc[mi][2 * ks + 1][1]);
                pa[mi][ks][3] = h2exp(s_acc[mi][2 * ks + 1][2], s_acc[mi][2 * ks + 1][3]);
            }

        #pragma unroll
        for (int mi = 0; mi < 2; ++mi)
            #pragma unroll
            for (int ks = 0; ks < 4; ++ks)
                MMA16816(l_acc[mi], pa[mi][ks], ONE2, ONE2);

        const uint32_t vd = kd + 8192;
        #pragma unroll
        for (int ks = 0; ks < 4; ++ks) {
            uint32_t vb[8][2];
            #pragma unroll
            for (int g = 0; g < 4; ++g) {
                int ch = g * 16 + b_r;
                uint32_t va = vd + (uint32_t)ch * 128 +
                              (((uint32_t)(b_c + ks * 32)) ^ ((uint32_t)((ch & 7) << 4)));
                LDM4(vb[2 * g][0], vb[2 * g][1], vb[2 * g + 1][0], vb[2 * g + 1][1], va);
            }
            #pragma unroll
            for (int mi = 0; mi < 2; ++mi)
                #pragma unroll
                for (int t = 0; t < 8; ++t)
                    MMA16816(o_acc[mi][t], pa[mi][ks], vb[t][0], vb[t][1]);
        }
        __syncthreads();
        mbar_arrive(MB + 32 + (j & 3) * 8);
    }

    const int lr = lane >> 2, lc = (lane & 3) * 2;
    const int t0q = qt * 128;
    #pragma unroll
    for (int mi = 0; mi < 2; ++mi) {
        float i0 = 1.f / l_acc[mi][0], i1 = 1.f / l_acc[mi][2];
        int trb = t0q + wid * 32 + mi * 16 + lr;
        #pragma unroll
        for (int t = 0; t < 8; ++t) {
            int c = h * 64 + t * 8 + lc;
            long sbase = ((long)b * 16 + (c >> 5)) * 65536;
            int k2 = (c & 31) * 2;
            long o0 = sbase + (long)trb * 64 + (k2 ^ ((trb & 6) << 3));
            *(__half2*)((char*)g_aT + o0) =
                __floats2half2_rn(o_acc[mi][t][0] * i0, o_acc[mi][t][1] * i0);
            int tr1 = trb + 8;
            long o1 = sbase + (long)tr1 * 64 + (k2 ^ ((tr1 & 6) << 3));
            *(__half2*)((char*)g_aT + o1) =
                __floats2half2_rn(o_acc[mi][t][2] * i1, o_acc[mi][t][3] * i1);
        }
    }
}

// ---------------- launch -----------------------------------------------------
extern "C" void kernel_launch(void* const* d_in, const int* in_sizes, int n_in,
                              void* d_out, int out_size) {
    const float* x      = (const float*)d_in[0];
    const float* norm_w = (const float*)d_in[1];
    const float* norm_b = (const float*)d_in[2];
    const float* qkv_w  = (const float*)d_in[3];
    const float* qkv_b  = (const float*)d_in[4];
    const float* proj_w = (const float*)d_in[5];
    const float* proj_b = (const float*)d_in[6];
    float* out = (float*)d_out;

    const int SMEM_QKV  = 4 * QKV_STAGE + 64;            // 65600
    const int SMEM_PROJ = 4 * PROJ_STAGE + 64;           // 98368
    const int SMEM_GN = CPG * GN_PAD * sizeof(float);    // 66112
    cudaFuncSetAttribute((const void*)gn_fused_kernel,
                         cudaFuncAttributeMaxDynamicSharedMemorySize, SMEM_GN);
    cudaFuncSetAttribute((const void*)gemm_qkv_kernel,
                         cudaFuncAttributeMaxDynamicSharedMemorySize, SMEM_QKV);
    cudaFuncSetAttribute((const void*)gemm_proj_kernel,
                         cudaFuncAttributeMaxDynamicSharedMemorySize, SMEM_PROJ);
    cudaFuncSetAttribute((const void*)flash_kernel,
                         cudaFuncAttributeMaxDynamicSharedMemorySize, FSMEM);

    // 1. fused GroupNorm + weight conversion
    gn_fused_kernel<<<BB * GROUPS, 512, SMEM_GN>>>(x, norm_w, norm_b, qkv_w, proj_w);
    // 2. QKV GEMM (512 threads)
    {
        dim3 grid(TT / 128, (3 * CC) / 128, BB);
        gemm_qkv_kernel<<<grid, 512, SMEM_QKV>>>(qkv_b);
    }
    // 3. flash attention
    {
        dim3 grid(TT / 128, BB * HEADS);
        flash_kernel<<<grid, 128, FSMEM>>>();
    }
    // 4. proj + bias + residual (512 threads)
    {
        dim3 grid(TT / 256, CC / 128, BB);
        gemm_proj_kernel<<<grid, 512, SMEM_PROJ>>>(proj_b, x, out);
    }
}

// round 17
// speedup vs baseline: 1.0176x; 1.0176x over previous
#include <cuda_runtime.h>
#include <cuda_fp16.h>
#include <math.h>
#include <stdint.h>

#define BB 8
#define CC 512
#define TT 1024
#define HEADS 8
#define CH 64
#define GROUPS 32
#define CPG 16
#define GN_EPS 1e-5f

// ---------------- scratch (fp16) ---------------------------------------------
// GEMM operands: [k-iter][row][32 halves], SW64 swizzle: kbyte ^ ((row&6)<<3)
__device__ __align__(1024) __half g_xnT[BB * TT * CC];
__device__ __align__(1024) __half g_qkvw[3 * CC * CC];
__device__ __align__(1024) __half g_projw[CC * CC];
__device__ __align__(1024) __half g_aT[BB * TT * CC];
// Flash tiles: contiguous per tile, 128B rows, SW128 swizzle: byte ^ ((row&7)<<4)
__device__ __align__(1024) __half g_qblk[BB * HEADS * 8 * 128 * 64];
__device__ __align__(1024) __half g_kblk[BB * HEADS * 16 * 64 * 64];
__device__ __align__(1024) __half g_vblk[BB * HEADS * 16 * 64 * 64];

// ---------------- helpers ----------------------------------------------------
__device__ __forceinline__ uint32_t smem_u32(const void* p) {
    uint32_t a;
    asm("{ .reg .u64 t; cvta.to.shared.u64 t, %1; cvt.u32.u64 %0, t; }"
        : "=r"(a) : "l"(p));
    return a;
}
__device__ __forceinline__ float warp_sum(float v) {
    #pragma unroll
    for (int o = 16; o > 0; o >>= 1) v += __shfl_down_sync(0xffffffffu, v, o);
    return v;
}
__device__ __forceinline__ uint32_t h2exp(float a, float b) {
    const float C = 0.1803368802f;    // 0.125 * log2(e)
    const float D = -5.7707801636f;   // -4 * log2(e)
    __half2 h = __floats2half2_rn(fmaf(a, C, D), fmaf(b, C, D));
    uint32_t r = *(uint32_t*)&h;
    uint32_t o;
    asm("ex2.approx.f16x2 %0, %1;" : "=r"(o) : "r"(r));
    return o;
}

#define LDM4(r0, r1, r2, r3, addr) \
    asm volatile("ldmatrix.sync.aligned.m8n8.x4.shared.b16 {%0,%1,%2,%3}, [%4];" \
                 : "=r"(r0), "=r"(r1), "=r"(r2), "=r"(r3) : "r"(addr))

#define MMA16816(d, a, b0v, b1v) \
    asm volatile("mma.sync.aligned.m16n8k16.row.col.f32.f16.f16.f32 " \
                 "{%0,%1,%2,%3}, {%4,%5,%6,%7}, {%8,%9}, {%0,%1,%2,%3};" \
                 : "+f"((d)[0]), "+f"((d)[1]), "+f"((d)[2]), "+f"((d)[3]) \
                 : "r"((a)[0]), "r"((a)[1]), "r"((a)[2]), "r"((a)[3]), \
                   "r"(b0v), "r"(b1v))

// ---------------- mbarrier + bulk copy helpers -------------------------------
__device__ __forceinline__ void mbar_init(uint32_t a, uint32_t cnt) {
    asm volatile("mbarrier.init.shared.b64 [%0], %1;" :: "r"(a), "r"(cnt) : "memory");
}
__device__ __forceinline__ void mbar_expect_tx(uint32_t a, uint32_t bytes) {
    asm volatile("mbarrier.arrive.expect_tx.shared.b64 _, [%0], %1;"
                 :: "r"(a), "r"(bytes) : "memory");
}
__device__ __forceinline__ void mbar_arrive(uint32_t a) {
    asm volatile("mbarrier.arrive.shared.b64 _, [%0];" :: "r"(a) : "memory");
}
__device__ __forceinline__ void mbar_wait(uint32_t a, uint32_t phase) {
    asm volatile(
        "{\n\t.reg .pred P;\n\t"
        "WL%=:\n\t"
        "mbarrier.try_wait.parity.acquire.cta.shared::cta.b64 P, [%0], %1, 0x989680;\n\t"
        "@P bra.uni WD%=;\n\t"
        "bra.uni WL%=;\n\t"
        "WD%=:\n\t}"
        :: "r"(a), "r"(phase) : "memory");
}
__device__ __forceinline__ void bulk_g2s(uint32_t dst, const void* src,
                                         uint32_t bytes, uint32_t mbar) {
    asm volatile(
        "cp.async.bulk.shared::cluster.global.mbarrier::complete_tx::bytes "
        "[%0], [%1], %2, [%3];"
        :: "r"(dst), "l"(src), "r"(bytes), "r"(mbar) : "memory");
}

// ---------------- fused GroupNorm (+ weight cvt tail, blocked outputs) -------
#define GN_PAD 1033
__global__ __launch_bounds__(512) void gn_fused_kernel(
    const float* __restrict__ x, const float* __restrict__ w,
    const float* __restrict__ bias,
    const float* __restrict__ qkvw, const float* __restrict__ projw) {
    extern __shared__ float sbuf[];
    const int bg = blockIdx.x;
    const int tid = threadIdx.x;
    const float* p = x + (long)bg * CPG * TT;

    float s = 0.f, ss = 0.f;
    #pragma unroll
    for (int i = tid; i < CPG * TT; i += 512) {
        float v = p[i];
        sbuf[(i >> 10) * GN_PAD + (i & 1023)] = v;
        s += v; ss += v * v;
    }
    __shared__ float shs[16], shss[16], bc[2];
    int lane = tid & 31, wid = tid >> 5;
    s = warp_sum(s); ss = warp_sum(ss);
    if (lane == 0) { shs[wid] = s; shss[wid] = ss; }
    __syncthreads();
    if (tid < 32) {
        s  = (lane < 16) ? shs[lane]  : 0.f;
        ss = (lane < 16) ? shss[lane] : 0.f;
        s = warp_sum(s); ss = warp_sum(ss);
        if (lane == 0) {
            const float inv_n = 1.f / (float)(CPG * TT);
            float mu = s * inv_n;
            float var = ss * inv_n - mu * mu;
            bc[0] = mu;
            bc[1] = rsqrtf(var + GN_EPS);
        }
    }
    __syncthreads();
    const float mu = bc[0], rs = bc[1];
    const int b = bg >> 5, g = bg & 31;
    const int cl = tid & 15;
    const int c = g * CPG + cl;
    const float wc = w[c] * rs;
    const float bb = bias[c] - mu * wc;
    char* xbase = (char*)g_xnT + ((long)b * 16 + (c >> 5)) * 65536;
    const int k2 = (c & 31) * 2;
    #pragma unroll
    for (int j = tid; j < CPG * TT; j += 512) {
        int t = j >> 4;
        float v = sbuf[cl * GN_PAD + t];
        long off = (long)t * 64 + (k2 ^ ((t & 6) << 3));
        *(__half*)(xbase + off) = __float2half(fmaf(v, wc, bb));
    }
    for (int i = bg * 512 + tid; i < 4 * CC * CC; i += 256 * 512) {
        if (i < 3 * CC * CC) {
            int m = i >> 9, cc2 = i & 511;
            long off = (long)(cc2 >> 5) * 98304 + (long)m * 64 +
                       (((cc2 & 31) * 2) ^ ((m & 6) << 3));
            *(__half*)((char*)g_qkvw + off) = __float2half(qkvw[i]);
        } else {
            int j = i - 3 * CC * CC;
            int m = j >> 9, cc2 = j & 511;
            long off = (long)(cc2 >> 5) * 32768 + (long)m * 64 +
                       (((cc2 & 31) * 2) ^ ((m & 6) << 3));
            *(__half*)((char*)g_projw + off) = __float2half(projw[j]);
        }
    }
}

#define EPI_STRIDE 136

// ---------------- QKV GEMM (256 threads, bulk ring; blocked qkv epilogue) ----
#define QKV_STAGE 16384
__global__ __launch_bounds__(256) void gemm_qkv_kernel(const float* __restrict__ bias) {
    extern __shared__ char smem[];
    constexpr int BM = 128, BN = 128, NT = 8, NT2 = 4;
    const uint32_t sb = smem_u32(smem);
    const uint32_t MB = sb + 4 * QKV_STAGE;
    const int tid = threadIdx.x;
    const int wid = tid >> 5, lane = tid & 31;
    const int wm = wid & 3, wn = wid >> 2;

    const int m0 = blockIdx.y * BM;
    const int n0 = blockIdx.x * BN;
    const int z = blockIdx.z;

    const char* Asrc = (const char*)g_qkvw + (long)m0 * 64;
    const char* Bsrc = (const char*)g_xnT + (long)z * 16 * 65536 + (long)n0 * 64;

    if (tid == 0) {
        #pragma unroll
        for (int s = 0; s < 4; ++s) { mbar_init(MB + s * 8, 1); mbar_init(MB + 32 + s * 8, 256); }
    }
    __syncthreads();
    if (tid == 0) {
        #pragma unroll
        for (int s = 0; s < 3; ++s) {
            mbar_expect_tx(MB + s * 8, QKV_STAGE);
            bulk_g2s(sb + s * QKV_STAGE, Asrc + (long)s * 98304, BM * 64, MB + s * 8);
            bulk_g2s(sb + s * QKV_STAGE + BM * 64, Bsrc + (long)s * 65536, BN * 64, MB + s * 8);
        }
    }

    float acc[2][NT][4] = {};
    const uint32_t sw = (lane & 6) << 3;
    const uint32_t a_row = (uint32_t)(wm * 32 + (lane & 15)) * 64;
    const uint32_t a_ch  = (uint32_t)((lane >> 4) << 4);
    const uint32_t b_row = (uint32_t)(wn * 64 + ((lane >> 4) << 3) + (lane & 7)) * 64;
    const uint32_t b_ch  = (uint32_t)(((lane >> 3) & 1) << 4);

    for (int i = 0; i < 16; ++i) {
        if (tid == 0 && i + 3 < 16) {
            int bu = (i + 3) & 3;
            if (i >= 1) mbar_wait(MB + 32 + bu * 8, ((i - 1) >> 2) & 1);
            mbar_expect_tx(MB + bu * 8, QKV_STAGE);
            bulk_g2s(sb + bu * QKV_STAGE, Asrc + (long)(i + 3) * 98304, BM * 64, MB + bu * 8);
            bulk_g2s(sb + bu * QKV_STAGE + BM * 64, Bsrc + (long)(i + 3) * 65536, BN * 64, MB + bu * 8);
        }
        mbar_wait(MB + (i & 3) * 8, (i >> 2) & 1);
        const uint32_t sA = sb + (i & 3) * QKV_STAGE;
        const uint32_t sB = sA + BM * 64;
        #pragma unroll
        for (int half = 0; half < 2; ++half) {
            uint32_t af[2][4];
            #pragma unroll
            for (int mi = 0; mi < 2; ++mi) {
                uint32_t ad = sA + a_row + mi * 1024 + (((uint32_t)(half * 32) + a_ch) ^ sw);
                LDM4(af[mi][0], af[mi][1], af[mi][2], af[mi][3], ad);
            }
            uint32_t bf[NT][2];
            #pragma unroll
            for (int g = 0; g < NT2; ++g) {
                uint32_t bd = sB + b_row + g * 1024 + (((uint32_t)(half * 32) + b_ch) ^ sw);
                LDM4(bf[2 * g][0], bf[2 * g][1], bf[2 * g + 1][0], bf[2 * g + 1][1], bd);
            }
            #pragma unroll
            for (int mi = 0; mi < 2; ++mi)
                #pragma unroll
                for (int ni = 0; ni < NT; ++ni)
                    MMA16816(acc[mi][ni], af[mi], bf[ni][0], bf[ni][1]);
        }
        mbar_arrive(MB + 32 + (i & 3) * 8);
    }
    __syncthreads();

    const int lr = lane >> 2;
    const int lc = (lane & 3) * 2;
    __half* stg = (__half*)smem;
    #pragma unroll
    for (int mi = 0; mi < 2; ++mi) {
        #pragma unroll
        for (int rs = 0; rs < 2; ++rs) {
            const int rl = wm * 32 + mi * 16 + rs * 8 + lr;
            const int r = m0 + rl;
            float bv = bias[r];
            int rm = r % 192;
            int h = r / 192;
            bool isv = (rm >= 128);
            #pragma unroll
            for (int ni = 0; ni < NT; ++ni) {
                int cl = wn * 64 + ni * 8 + lc;
                __half h0 = __float2half(acc[mi][ni][rs * 2 + 0] + bv);
                __half h1 = __float2half(acc[mi][ni][rs * 2 + 1] + bv);
                stg[cl * EPI_STRIDE + rl] = h0;
                stg[(cl + 1) * EPI_STRIDE + rl] = h1;
                if (isv) {
                    int c = n0 + cl;
                    int ch = rm - 128;
                    long vb = (((long)(z * 8 + h) * 16) + (c >> 6)) * 8192;
                    long off = vb + (long)ch * 128 + (((c & 63) * 2) ^ ((ch & 7) << 4));
                    *(__half2*)((char*)g_vblk + off) = __halves2half2(h0, h1);
                }
            }
        }
    }
    __syncthreads();
    #pragma unroll
    for (int task = tid; task < BN * 16; task += 256) {
        int cl = task >> 4, seg = task & 15;
        int m = m0 + seg * 8;
        int rm = m % 192;
        if (rm < 128) {
            int h = m / 192;
            int tg = n0 + cl;
            uint4 v = *(uint4*)&stg[cl * EPI_STRIDE + seg * 8];
            if (rm < 64) {
                long qb = (((long)(z * 8 + h) * 8) + (tg >> 7)) * 16384;
                int r = tg & 127;
                long off = qb + (long)r * 128 + ((rm * 2) ^ ((r & 7) << 4));
                *(uint4*)((char*)g_qblk + off) = v;
            } else {
                long kb = (((long)(z * 8 + h) * 16) + (tg >> 6)) * 8192;
                int tok = tg & 63;
                long off = kb + (long)tok * 128 + (((rm - 64) * 2) ^ ((tok & 7) << 4));
                *(uint4*)((char*)g_kblk + off) = v;
            }
        }
    }
}

// ---------------- PROJ GEMM (256 threads, BN=128, 2+ CTAs/SM overlap) --------
#define PROJ_STAGE 16384
__global__ __launch_bounds__(256) void gemm_proj_kernel(
    const float* __restrict__ bias, const float* __restrict__ xres,
    float* __restrict__ out) {
    extern __shared__ char smem[];
    constexpr int BM = 128, BN = 128, NT = 8, NT2 = 4;
    const uint32_t sb = smem_u32(smem);
    const uint32_t MB = sb + 4 * PROJ_STAGE;
    const int tid = threadIdx.x;
    const int wid = tid >> 5, lane = tid & 31;
    const int wm = wid & 3, wn = wid >> 2;     // 4m x 2n of 32x64 tiles

    const int m0 = blockIdx.y * BM;
    const int n0 = blockIdx.x * BN;
    const int z = blockIdx.z;

    const char* Asrc = (const char*)g_projw + (long)m0 * 64;
    const char* Bsrc = (const char*)g_aT + (long)z * 16 * 65536 + (long)n0 * 64;

    if (tid == 0) {
        #pragma unroll
        for (int s = 0; s < 4; ++s) { mbar_init(MB + s * 8, 1); mbar_init(MB + 32 + s * 8, 256); }
    }
    __syncthreads();
    if (tid == 0) {
        #pragma unroll
        for (int s = 0; s < 3; ++s) {
            mbar_expect_tx(MB + s * 8, PROJ_STAGE);
            bulk_g2s(sb + s * PROJ_STAGE, Asrc + (long)s * 32768, BM * 64, MB + s * 8);
            bulk_g2s(sb + s * PROJ_STAGE + BM * 64, Bsrc + (long)s * 65536, BN * 64, MB + s * 8);
        }
    }

    float acc[2][NT][4] = {};
    const uint32_t sw = (lane & 6) << 3;
    const uint32_t a_row = (uint32_t)(wm * 32 + (lane & 15)) * 64;
    const uint32_t a_ch  = (uint32_t)((lane >> 4) << 4);
    const uint32_t b_row = (uint32_t)(wn * 64 + ((lane >> 4) << 3) + (lane & 7)) * 64;
    const uint32_t b_ch  = (uint32_t)(((lane >> 3) & 1) << 4);

    for (int i = 0; i < 16; ++i) {
        if (tid == 0 && i + 3 < 16) {
            int bu = (i + 3) & 3;
            if (i >= 1) mbar_wait(MB + 32 + bu * 8, ((i - 1) >> 2) & 1);
            mbar_expect_tx(MB + bu * 8, PROJ_STAGE);
            bulk_g2s(sb + bu * PROJ_STAGE, Asrc + (long)(i + 3) * 32768, BM * 64, MB + bu * 8);
            bulk_g2s(sb + bu * PROJ_STAGE + BM * 64, Bsrc + (long)(i + 3) * 65536, BN * 64, MB + bu * 8);
        }
        mbar_wait(MB + (i & 3) * 8, (i >> 2) & 1);
        const uint32_t sA = sb + (i & 3) * PROJ_STAGE;
        const uint32_t sB = sA + BM * 64;
        #pragma unroll
        for (int half = 0; half < 2; ++half) {
            uint32_t af[2][4];
            #pragma unroll
            for (int mi = 0; mi < 2; ++mi) {
                uint32_t ad = sA + a_row + mi * 1024 + (((uint32_t)(half * 32) + a_ch) ^ sw);
                LDM4(af[mi][0], af[mi][1], af[mi][2], af[mi][3], ad);
            }
            uint32_t bf[NT][2];
            #pragma unroll
            for (int g = 0; g < NT2; ++g) {
                uint32_t bd = sB + b_row + g * 1024 + (((uint32_t)(half * 32) + b_ch) ^ sw);
                LDM4(bf[2 * g][0], bf[2 * g][1], bf[2 * g + 1][0], bf[2 * g + 1][1], bd);
            }
            #pragma unroll
            for (int mi = 0; mi < 2; ++mi)
                #pragma unroll
                for (int ni = 0; ni < NT; ++ni)
                    MMA16816(acc[mi][ni], af[mi], bf[ni][0], bf[ni][1]);
        }
        mbar_arrive(MB + 32 + (i & 3) * 8);
    }

    const int lr = lane >> 2;
    const int lc = (lane & 3) * 2;
    #pragma unroll
    for (int mi = 0; mi < 2; ++mi) {
        #pragma unroll
        for (int rs = 0; rs < 2; ++rs) {
            const int r = m0 + wm * 32 + mi * 16 + rs * 8 + lr;
            float bv = bias[r];
            long rowb = ((long)z * CC + r) * TT;
            #pragma unroll
            for (int ni = 0; ni < NT; ++ni) {
                int c = n0 + wn * 64 + ni * 8 + lc;
                float2 xv = *(const float2*)&xres[rowb + c];
                float2 o = make_float2(acc[mi][ni][rs * 2 + 0] + bv + xv.x,
                                       acc[mi][ni][rs * 2 + 1] + bv + xv.y);
                *(float2*)&out[rowb + c] = o;
            }
        }
    }
}

// ---------------- flash attention (bulk ring, no per-iter syncthreads) -------
#define FQB 16384
#define FSTG2 16384
#define FSMEM (FQB + 4 * FSTG2 + 64)   // 82048

__global__ __launch_bounds__(128) void flash_kernel() {
    extern __shared__ char smem[];
    const uint32_t sb = smem_u32(smem);
    const uint32_t MB = sb + FQB + 4 * FSTG2;
    const int tid = threadIdx.x, wid = tid >> 5, lane = tid & 31;
    const int qt = blockIdx.x;
    const int z = blockIdx.y;
    const int b = z >> 3, h = z & 7;
    const uint32_t ONE2 = 0x3C003C00u;

    const char* Qsrc = (const char*)g_qblk + (((long)(b * 8 + h) * 8) + qt) * 16384;
    const char* Ksrc = (const char*)g_kblk + ((long)(b * 8 + h) * 16) * 8192;
    const char* Vsrc = (const char*)g_vblk + ((long)(b * 8 + h) * 16) * 8192;

    if (tid == 0) {
        #pragma unroll
        for (int s = 0; s < 4; ++s) { mbar_init(MB + s * 8, 1); mbar_init(MB + 32 + s * 8, 128); }
    }
    __syncthreads();
    if (tid == 0) {
        mbar_expect_tx(MB + 0, FQB + FSTG2);
        bulk_g2s(sb, Qsrc, FQB, MB + 0);
        bulk_g2s(sb + FQB, Ksrc, 8192, MB + 0);
        bulk_g2s(sb + FQB + 8192, Vsrc, 8192, MB + 0);
        #pragma unroll
        for (int s = 1; s < 3; ++s) {
            mbar_expect_tx(MB + s * 8, FSTG2);
            bulk_g2s(sb + FQB + s * FSTG2, Ksrc + (long)s * 8192, 8192, MB + s * 8);
            bulk_g2s(sb + FQB + s * FSTG2 + 8192, Vsrc + (long)s * 8192, 8192, MB + s * 8);
        }
    }

    float o_acc[2][8][4] = {};
    float l_acc[2][4] = {};
    uint32_t qf[2][4][4];
    const int a_r16 = lane & 15;
    const int a_c   = (lane >> 4) << 4;
    const int b_r   = ((lane >> 4) << 3) + (lane & 7);
    const int b_c   = ((lane >> 3) & 1) << 4;

    for (int j = 0; j < 16; ++j) {
        if (tid == 0 && j + 3 < 16) {
            int bu = (j + 3) & 3;
            if (j >= 1) mbar_wait(MB + 32 + bu * 8, ((j - 1) >> 2) & 1);
            mbar_expect_tx(MB + bu * 8, FSTG2);
            bulk_g2s(sb + FQB + bu * FSTG2, Ksrc + (long)(j + 3) * 8192, 8192, MB + bu * 8);
            bulk_g2s(sb + FQB + bu * FSTG2 + 8192, Vsrc + (long)(j + 3) * 8192, 8192, MB + bu * 8);
        }
        mbar_wait(MB + (j & 3) * 8, (j >> 2) & 1);

        if (j == 0) {
            #pragma unroll
            for (int mi = 0; mi < 2; ++mi) {
                int r = wid * 32 + mi * 16 + a_r16;
                uint32_t rowb = sb + (uint32_t)r * 128;
                uint32_t swz = (uint32_t)((r & 7) << 4);
                #pragma unroll
                for (int ks = 0; ks < 4; ++ks)
                    LDM4(qf[mi][ks][0], qf[mi][ks][1], qf[mi][ks][2], qf[mi][ks][3],
                         rowb + (((uint32_t)(a_c + ks * 32)) ^ swz));
            }
        }

        const uint32_t kd = sb + FQB + (j & 3) * FSTG2;
        float s_acc[2][8][4] = {};

        #pragma unroll
        for (int ks = 0; ks < 4; ++ks) {
            uint32_t bh[8][2];
            #pragma unroll
            for (int g = 0; g < 4; ++g) {
                int tok = g * 16 + b_r;
                uint32_t ba = kd + (uint32_t)tok * 128 +
                              (((uint32_t)(b_c + ks * 32)) ^ ((uint32_t)((tok & 7) << 4)));
                LDM4(bh[2 * g][0], bh[2 * g][1], bh[2 * g + 1][0], bh[2 * g + 1][1], ba);
            }
            #pragma unroll
            for (int mi = 0; mi < 2; ++mi)
                #pragma unroll
                for (int t = 0; t < 8; ++t)
                    MMA16816(s_acc[mi][t], qf[mi][ks], bh[t][0], bh[t][1]);
        }

        uint32_t pa[2][4][4];
        #pragma unroll
        for (int mi = 0; mi < 2; ++mi)
            #pragma unroll
            for (int ks = 0; ks < 4; ++ks) {
                pa[mi][ks][0] = h2exp(s_acc[mi][2 * ks][0], s_acc[mi][2 * ks][1]);
                pa[mi][ks][1] = h2exp(s_acc[mi][2 * ks][2], s_acc[mi][2 * ks][3]);
                pa[mi][ks][2] = h2exp(s_acc[mi][2 * ks + 1][0], s_acc[mi][2 * ks + 1][1]);
                pa[mi][ks][3] = h2exp(s_acc[mi][2 * ks + 1][2], s_acc[mi][2 * ks + 1][3]);
            }

        #pragma unroll
        for (int mi = 0; mi < 2; ++mi)
            #pragma unroll
            for (int ks = 0; ks < 4; ++ks)
                MMA16816(l_acc[mi], pa[mi][ks], ONE2, ONE2);

        const uint32_t vd = kd + 8192;
        #pragma unroll
        for (int ks = 0; ks < 4; ++ks) {
            uint32_t vb[8][2];
            #pragma unroll
            for (int g = 0; g < 4; ++g) {
                int ch = g * 16 + b_r;
                uint32_t va = vd + (uint32_t)ch * 128 +
                              (((uint32_t)(b_c + ks * 32)) ^ ((uint32_t)((ch & 7) << 4)));
                LDM4(vb[2 * g][0], vb[2 * g][1], vb[2 * g + 1][0], vb[2 * g + 1][1], va);
            }
            #pragma unroll
            for (int mi = 0; mi < 2; ++mi)
                #pragma unroll
                for (int t = 0; t < 8; ++t)
                    MMA16816(o_acc[mi][t], pa[mi][ks], vb[t][0], vb[t][1]);
        }
        // per-thread arrival replaces __syncthreads(): empty mbar counts 128
        mbar_arrive(MB + 32 + (j & 3) * 8);
    }

    const int lr = lane >> 2, lc = (lane & 3) * 2;
    const int t0q = qt * 128;
    #pragma unroll
    for (int mi = 0; mi < 2; ++mi) {
        float i0 = 1.f / l_acc[mi][0], i1 = 1.f / l_acc[mi][2];
        int trb = t0q + wid * 32 + mi * 16 + lr;
        #pragma unroll
        for (int t = 0; t < 8; ++t) {
            int c = h * 64 + t * 8 + lc;
            long sbase = ((long)b * 16 + (c >> 5)) * 65536;
            int k2 = (c & 31) * 2;
            long o0 = sbase + (long)trb * 64 + (k2 ^ ((trb & 6) << 3));
            *(__half2*)((char*)g_aT + o0) =
                __floats2half2_rn(o_acc[mi][t][0] * i0, o_acc[mi][t][1] * i0);
            int tr1 = trb + 8;
            long o1 = sbase + (long)tr1 * 64 + (k2 ^ ((tr1 & 6) << 3));
            *(__half2*)((char*)g_aT + o1) =
                __floats2half2_rn(o_acc[mi][t][2] * i1, o_acc[mi][t][3] * i1);
        }
    }
}

// ---------------- launch -----------------------------------------------------
extern "C" void kernel_launch(void* const* d_in, const int* in_sizes, int n_in,
                              void* d_out, int out_size) {
    const float* x      = (const float*)d_in[0];
    const float* norm_w = (const float*)d_in[1];
    const float* norm_b = (const float*)d_in[2];
    const float* qkv_w  = (const float*)d_in[3];
    const float* qkv_b  = (const float*)d_in[4];
    const float* proj_w = (const float*)d_in[5];
    const float* proj_b = (const float*)d_in[6];
    float* out = (float*)d_out;

    const int SMEM_QKV  = 4 * QKV_STAGE + 64;            // 65600
    const int SMEM_PROJ = 4 * PROJ_STAGE + 64;           // 65600
    const int SMEM_GN = CPG * GN_PAD * sizeof(float);    // 66112
    cudaFuncSetAttribute((const void*)gn_fused_kernel,
                         cudaFuncAttributeMaxDynamicSharedMemorySize, SMEM_GN);
    cudaFuncSetAttribute((const void*)gemm_qkv_kernel,
                         cudaFuncAttributeMaxDynamicSharedMemorySize, SMEM_QKV);
    cudaFuncSetAttribute((const void*)gemm_proj_kernel,
                         cudaFuncAttributeMaxDynamicSharedMemorySize, SMEM_PROJ);
    cudaFuncSetAttribute((const void*)flash_kernel,
                         cudaFuncAttributeMaxDynamicSharedMemorySize, FSMEM);

    // 1. fused GroupNorm + weight conversion
    gn_fused_kernel<<<BB * GROUPS, 512, SMEM_GN>>>(x, norm_w, norm_b, qkv_w, proj_w);
    // 2. QKV GEMM
    {
        dim3 grid(TT / 128, (3 * CC) / 128, BB);
        gemm_qkv_kernel<<<grid, 256, SMEM_QKV>>>(qkv_b);
    }
    // 3. flash attention
    {
        dim3 grid(TT / 128, BB * HEADS);
        flash_kernel<<<grid, 128, FSMEM>>>();
    }
    // 4. proj + bias + residual (BN=128, 256 CTAs → epilogue/mainloop overlap)
    {
        dim3 grid(TT / 128, CC / 128, BB);
        gemm_proj_kernel<<<grid, 256, SMEM_PROJ>>>(proj_b, x, out);
    }
}